// round 2
// baseline (speedup 1.0000x reference)
#include <cuda_runtime.h>
#include <cuda_fp16.h>
#include <cstdint>

#define DIN  4096
#define DOUT 4096
#define MROWS 8192   // 4 * 2048

// Scratch (device globals; no allocations allowed)
static __device__ __align__(128) __half g_qx[(size_t)MROWS * DIN];   // 64 MB: quantized activations (exact ints)
static __device__ __align__(128) __half g_wq[(size_t)DOUT * DIN];    // 32 MB: dequantized weights (fp16)
static __device__ float g_sa[MROWS];
static __device__ float g_scale[DIN];

// ---------------------------------------------------------------- scale
__global__ void scale_kernel(const float* __restrict__ log_scale) {
    int i = blockIdx.x * 256 + threadIdx.x;
    if (i < DIN) {
        float s = expf(log_scale[i]);
        g_scale[i] = fminf(fmaxf(s, 1e-4f), 1e4f);
    }
}

// ---------------------------------------------------------------- activation quant (per row, symmetric 8-bit)
__global__ void xquant_kernel(const float* __restrict__ x) {
    int row = blockIdx.x;
    const float* xr = x + (size_t)row * DIN;
    float v[16];
    float amax = 0.f;
#pragma unroll
    for (int j = 0; j < 16; j++) {
        int k = threadIdx.x + j * 256;
        v[j] = xr[k] / g_scale[k];
        amax = fmaxf(amax, fabsf(v[j]));
    }
#pragma unroll
    for (int o = 16; o > 0; o >>= 1)
        amax = fmaxf(amax, __shfl_xor_sync(0xffffffffu, amax, o));
    __shared__ float red[8];
    __shared__ float s_scale;
    if ((threadIdx.x & 31) == 0) red[threadIdx.x >> 5] = amax;
    __syncthreads();
    if (threadIdx.x == 0) {
        float m = red[0];
#pragma unroll
        for (int i = 1; i < 8; i++) m = fmaxf(m, red[i]);
        m = fmaxf(m, 1e-5f);
        float s = m / 127.f;
        s_scale = s;
        g_sa[row] = s;
    }
    __syncthreads();
    float s = s_scale;
    __half* q = g_qx + (size_t)row * DIN;
#pragma unroll
    for (int j = 0; j < 16; j++) {
        int k = threadIdx.x + j * 256;
        float t = rintf(v[j] / s);              // round-half-even matches jnp.round
        t = fminf(fmaxf(t, -128.f), 127.f);
        q[k] = __float2half_rn(t);              // exact integer
    }
}

// ---------------------------------------------------------------- weight fake-quant (one warp per 128-group, 4-bit asym)
__global__ void wquant_kernel(const float* __restrict__ w) {
    int g = blockIdx.x * 8 + (threadIdx.x >> 5);       // group id, 131072 total
    int lane = threadIdx.x & 31;
    int row = g >> 5;          // D_OUT row
    int grp = g & 31;          // group within row
    const float* wr = w + (size_t)row * DIN + grp * 128;
    const float* sc = g_scale + grp * 128;
    float v[4];
    float mx = -3.4e38f, mn = 3.4e38f;
#pragma unroll
    for (int j = 0; j < 4; j++) {
        int k = lane + j * 32;
        v[j] = wr[k] * sc[k];
        mx = fmaxf(mx, v[j]);
        mn = fminf(mn, v[j]);
    }
#pragma unroll
    for (int o = 16; o > 0; o >>= 1) {
        mx = fmaxf(mx, __shfl_xor_sync(0xffffffffu, mx, o));
        mn = fminf(mn, __shfl_xor_sync(0xffffffffu, mn, o));
    }
    float s = fmaxf(mx - mn, 1e-5f) / 15.f;
    float z = fminf(fmaxf(-rintf(mn / s), 0.f), 15.f);
    __half* dst = g_wq + (size_t)row * DIN + grp * 128;
#pragma unroll
    for (int j = 0; j < 4; j++) {
        int k = lane + j * 32;
        float q = fminf(fmaxf(rintf(v[j] / s) + z, 0.f), 15.f);
        dst[k] = __float2half_rn((q - z) * s);
    }
}

// ---------------------------------------------------------------- GEMM: out[M,N] = (qx @ wq^T) * sa[row] + bias
#define BM 128
#define BN 128
#define BK 32
#define LDS_PAD 8
#define SROW (BK + LDS_PAD)   // 40 halves per smem row -> conflict-free ldmatrix

__global__ __launch_bounds__(256, 2) void gemm_kernel(const float* __restrict__ bias,
                                                      float* __restrict__ out) {
    __shared__ __align__(16) __half As[2][BM][SROW];
    __shared__ __align__(16) __half Bs[2][BN][SROW];

    const int tid  = threadIdx.x;
    const int warp = tid >> 5;
    const int lane = tid & 31;
    const int m0 = blockIdx.y * BM;
    const int n0 = blockIdx.x * BN;
    const int wm = (warp & 1) * 64;    // warp tile 64x32
    const int wn = (warp >> 1) * 32;

    const __half* gA = g_qx + (size_t)m0 * DIN;
    const __half* gB = g_wq + (size_t)n0 * DIN;

    float acc[4][4][4];
#pragma unroll
    for (int a = 0; a < 4; a++)
#pragma unroll
        for (int b = 0; b < 4; b++)
#pragma unroll
            for (int c = 0; c < 4; c++) acc[a][b][c] = 0.f;

#define LOAD_TILE(KK, BUF)                                                            \
    {                                                                                 \
        _Pragma("unroll")                                                             \
        for (int l = 0; l < 2; l++) {                                                 \
            int idx = tid + l * 256;                                                  \
            int r  = idx >> 2;                                                        \
            int cc = (idx & 3) << 3;                                                  \
            uint32_t da = (uint32_t)__cvta_generic_to_shared(&As[BUF][r][cc]);        \
            const void* pa = gA + (size_t)r * DIN + (KK) + cc;                        \
            asm volatile("cp.async.cg.shared.global [%0], [%1], 16;\n" ::"r"(da), "l"(pa)); \
            uint32_t db = (uint32_t)__cvta_generic_to_shared(&Bs[BUF][r][cc]);        \
            const void* pb = gB + (size_t)r * DIN + (KK) + cc;                        \
            asm volatile("cp.async.cg.shared.global [%0], [%1], 16;\n" ::"r"(db), "l"(pb)); \
        }                                                                             \
        asm volatile("cp.async.commit_group;\n");                                     \
    }

    int buf = 0;
    LOAD_TILE(0, 0);

    const int NK = DIN / BK;   // 128
    for (int it = 0; it < NK; it++) {
        if (it + 1 < NK) {
            LOAD_TILE((it + 1) * BK, buf ^ 1);
            asm volatile("cp.async.wait_group 1;\n");
        } else {
            asm volatile("cp.async.wait_group 0;\n");
        }
        __syncthreads();

#pragma unroll
        for (int ks = 0; ks < 2; ks++) {
            const int ko = ks * 16;
            uint32_t afr[4][4];
#pragma unroll
            for (int mt = 0; mt < 4; mt++) {
                int r = wm + mt * 16 + (lane & 15);
                int c = ko + ((lane >> 4) << 3);
                uint32_t addr = (uint32_t)__cvta_generic_to_shared(&As[buf][r][c]);
                asm volatile("ldmatrix.sync.aligned.m8n8.x4.shared.b16 {%0,%1,%2,%3}, [%4];\n"
                             : "=r"(afr[mt][0]), "=r"(afr[mt][1]),
                               "=r"(afr[mt][2]), "=r"(afr[mt][3])
                             : "r"(addr));
            }
            uint32_t bfr[4][2];
#pragma unroll
            for (int nt = 0; nt < 4; nt++) {
                int r = wn + nt * 8 + (lane & 7);
                int c = ko + (((lane >> 3) & 1) << 3);
                uint32_t addr = (uint32_t)__cvta_generic_to_shared(&Bs[buf][r][c]);
                asm volatile("ldmatrix.sync.aligned.m8n8.x2.shared.b16 {%0,%1}, [%2];\n"
                             : "=r"(bfr[nt][0]), "=r"(bfr[nt][1])
                             : "r"(addr));
            }
#pragma unroll
            for (int mt = 0; mt < 4; mt++)
#pragma unroll
                for (int nt = 0; nt < 4; nt++) {
                    asm volatile(
                        "mma.sync.aligned.m16n8k16.row.col.f32.f16.f16.f32 "
                        "{%0,%1,%2,%3}, {%4,%5,%6,%7}, {%8,%9}, {%0,%1,%2,%3};\n"
                        : "+f"(acc[mt][nt][0]), "+f"(acc[mt][nt][1]),
                          "+f"(acc[mt][nt][2]), "+f"(acc[mt][nt][3])
                        : "r"(afr[mt][0]), "r"(afr[mt][1]), "r"(afr[mt][2]), "r"(afr[mt][3]),
                          "r"(bfr[nt][0]), "r"(bfr[nt][1]));
                }
        }
        __syncthreads();
        buf ^= 1;
    }

    // Epilogue: out = sa[row]*acc + bias[col]
#pragma unroll
    for (int mt = 0; mt < 4; mt++) {
        int r0 = m0 + wm + mt * 16 + (lane >> 2);
        float sa0 = g_sa[r0];
        float sa1 = g_sa[r0 + 8];
#pragma unroll
        for (int nt = 0; nt < 4; nt++) {
            int c0 = n0 + wn + nt * 8 + ((lane & 3) << 1);
            float b0 = __ldg(bias + c0);
            float b1 = __ldg(bias + c0 + 1);
            out[(size_t)r0 * DOUT + c0]           = sa0 * acc[mt][nt][0] + b0;
            out[(size_t)r0 * DOUT + c0 + 1]       = sa0 * acc[mt][nt][1] + b1;
            out[(size_t)(r0 + 8) * DOUT + c0]     = sa1 * acc[mt][nt][2] + b0;
            out[(size_t)(r0 + 8) * DOUT + c0 + 1] = sa1 * acc[mt][nt][3] + b1;
        }
    }
}

// ---------------------------------------------------------------- launch
extern "C" void kernel_launch(void* const* d_in, const int* in_sizes, int n_in,
                              void* d_out, int out_size) {
    const float* x    = (const float*)d_in[0];
    const float* w    = (const float*)d_in[1];
    const float* bias = (const float*)d_in[2];
    const float* lsc  = (const float*)d_in[3];
    float* out = (float*)d_out;

    scale_kernel<<<16, 256>>>(lsc);
    xquant_kernel<<<MROWS, 256>>>(x);
    wquant_kernel<<<(DOUT * 32) / 8, 256>>>(w);
    gemm_kernel<<<dim3(DOUT / BN, MROWS / BM), 256>>>(bias, out);
}